// round 3
// baseline (speedup 1.0000x reference)
#include <cuda_runtime.h>
#include <cuda_bf16.h>

// Problem constants
#define BATCH   64
#define TSTEPS  1024
#define DIM     512          // D_in == D_out == 512
#define NCTA    128          // persistent grid size (<= 148 SMs -> co-resident)

// ---------------- scratch (device globals; no allocations allowed) ----------
__device__ float    g_xw[BATCH * TSTEPS * DIM];   // 134 MB precomputed x@W + b
__device__ float    g_h[2][BATCH * DIM];          // ping-pong hidden state
__device__ unsigned g_bar[TSTEPS];                // per-step grid barrier counters

// ============================================================================
// Kernel 1: XW = reshape(x,[B*T,512]) @ W[512,512] + bias   (fp32 SIMT GEMM)
// BM=128, BN=64, BK=16, 256 threads, 8x4 outputs per thread
// ============================================================================
#define BM 128
#define BN 64
#define BK 16

__global__ void __launch_bounds__(256) gemm_xw_kernel(
    const float* __restrict__ X,      // [65536, 512]
    const float* __restrict__ W,      // [512, 512]
    const float* __restrict__ bias,   // [512]
    float* __restrict__ XW)           // [65536, 512]
{
    __shared__ float As[BK * BM];     // transposed: As[k][m]
    __shared__ float Bs[BK * BN];     // Bs[k][n]

    const int tid = threadIdx.x;
    const int bm  = blockIdx.x * BM;
    const int bn  = blockIdx.y * BN;

    // A-load mapping: 128 rows x 16 k -> thread loads 2 float4 along k
    const int a_row = tid >> 1;
    const int a_k   = (tid & 1) * 8;
    // B-load mapping: 16 k x 64 n -> thread loads 1 float4 along n
    const int b_k   = tid >> 4;
    const int b_n   = (tid & 15) * 4;
    // compute mapping: 16x16 thread grid, 8 rows x 4 cols each
    const int ty = tid >> 4;
    const int tx = tid & 15;

    float acc[8][4];
#pragma unroll
    for (int i = 0; i < 8; i++)
#pragma unroll
        for (int j = 0; j < 4; j++) acc[i][j] = 0.f;

    for (int k0 = 0; k0 < DIM; k0 += BK) {
        // load A tile (transpose into As[k][m])
        float4 a0 = *(const float4*)&X[(size_t)(bm + a_row) * DIM + k0 + a_k];
        float4 a1 = *(const float4*)&X[(size_t)(bm + a_row) * DIM + k0 + a_k + 4];
        As[(a_k + 0) * BM + a_row] = a0.x;
        As[(a_k + 1) * BM + a_row] = a0.y;
        As[(a_k + 2) * BM + a_row] = a0.z;
        As[(a_k + 3) * BM + a_row] = a0.w;
        As[(a_k + 4) * BM + a_row] = a1.x;
        As[(a_k + 5) * BM + a_row] = a1.y;
        As[(a_k + 6) * BM + a_row] = a1.z;
        As[(a_k + 7) * BM + a_row] = a1.w;
        // load B tile
        *(float4*)&Bs[b_k * BN + b_n] =
            *(const float4*)&W[(size_t)(k0 + b_k) * DIM + bn + b_n];
        __syncthreads();

#pragma unroll
        for (int kk = 0; kk < BK; kk++) {
            float ar[8], br[4];
            *(float4*)&ar[0] = *(const float4*)&As[kk * BM + ty * 8];
            *(float4*)&ar[4] = *(const float4*)&As[kk * BM + ty * 8 + 4];
            *(float4*)&br[0] = *(const float4*)&Bs[kk * BN + tx * 4];
#pragma unroll
            for (int i = 0; i < 8; i++)
#pragma unroll
                for (int j = 0; j < 4; j++)
                    acc[i][j] = fmaf(ar[i], br[j], acc[i][j]);
        }
        __syncthreads();
    }

    // epilogue: add bias, store
    float4 bv = *(const float4*)&bias[bn + tx * 4];
#pragma unroll
    for (int i = 0; i < 8; i++) {
        float4 o;
        o.x = acc[i][0] + bv.x;
        o.y = acc[i][1] + bv.y;
        o.z = acc[i][2] + bv.z;
        o.w = acc[i][3] + bv.w;
        *(float4*)&XW[(size_t)(bm + ty * 8 + i) * DIM + bn + tx * 4] = o;
    }
}

// ============================================================================
// Kernel 2: persistent recurrent loop.
// 128 CTAs x 256 threads. CTA (bg, jg): b-rows [bg*8, bg*8+8), cols [jg*32,+32).
// Thread layout: warp = kq (k-quarter-of-64), lane = j_local.
// W_r slice lives in registers (64 floats/thread) for the whole kernel.
// Per step: stage h-tile (16KB, __ldcg, L2-coherent) -> 512 FFMA/thread ->
// cross-warp reduce in smem -> tanh -> store h ping-pong -> grid barrier.
// ============================================================================
__global__ void __launch_bounds__(256, 1) rnn_persistent_kernel(
    const float* __restrict__ Wr,     // [512, 512] row-major: Wr[k*512 + j]
    const float* __restrict__ xw,     // [B, T, 512]
    float* __restrict__ out)          // [B, 512]
{
    __shared__ float hs[8 * DIM];          // 16 KB staged h tile
    __shared__ float part[8 * 8 * 32];     // 8 KB partial sums [kq][bl][j]

    const int tid  = threadIdx.x;
    const int kq   = tid >> 5;             // warp id 0..7 -> k range [kq*64, +64)
    const int lane = tid & 31;             // j_local
    const int c    = blockIdx.x;
    const int b0   = (c >> 4) * 8;         // 8 batch-groups
    const int j0   = (c & 15) * 32;        // 16 column-groups

    // Load persistent W_r slice into registers: w_reg[i] = Wr[kq*64+i][j0+lane]
    float w_reg[64];
#pragma unroll
    for (int i = 0; i < 64; i++)
        w_reg[i] = Wr[(size_t)(kq * 64 + i) * DIM + j0 + lane];

    // reduction-phase mapping (reuse all 256 threads: 8 bl x 32 j)
    const int rbl = tid >> 5;
    const int rj  = lane;

    for (int t = 0; t < TSTEPS; t++) {
        const float* hcur = g_h[t & 1];

        // ---- stage h tile: 8 rows x 512 = 1024 float4, 4 per thread ----
        {
            const float4* src = (const float4*)(hcur + b0 * DIM);
#pragma unroll
            for (int q = 0; q < 4; q++) {
                int idx = tid + q * 256;
                float4 v = __ldcg(src + idx);        // bypass L1 (cross-CTA data)
                *(float4*)&hs[idx * 4] = v;
            }
        }
        __syncthreads();

        // ---- partial matmul: acc[bl] = sum_{k in kq-range} hs[bl][k]*w_reg ----
        float acc[8];
#pragma unroll
        for (int bl = 0; bl < 8; bl++) acc[bl] = 0.f;
#pragma unroll
        for (int bl = 0; bl < 8; bl++) {
            const float* hrow = &hs[bl * DIM + kq * 64];
#pragma unroll
            for (int i = 0; i < 64; i += 4) {
                float4 h4 = *(const float4*)&hrow[i];   // broadcast across lanes
                acc[bl] = fmaf(h4.x, w_reg[i + 0], acc[bl]);
                acc[bl] = fmaf(h4.y, w_reg[i + 1], acc[bl]);
                acc[bl] = fmaf(h4.z, w_reg[i + 2], acc[bl]);
                acc[bl] = fmaf(h4.w, w_reg[i + 3], acc[bl]);
            }
        }
#pragma unroll
        for (int bl = 0; bl < 8; bl++)
            part[kq * 256 + bl * 32 + lane] = acc[bl];
        __syncthreads();

        // ---- reduce over kq, add xw, tanh, write ----
        {
            float s = 0.f;
#pragma unroll
            for (int q = 0; q < 8; q++)
                s += part[q * 256 + rbl * 32 + rj];
            s += xw[((size_t)(b0 + rbl) * TSTEPS + t) * DIM + j0 + rj];
            float hv = tanhf(s);
            if (t == TSTEPS - 1) {
                out[(b0 + rbl) * DIM + j0 + rj] = hv;
            } else {
                g_h[(t + 1) & 1][(b0 + rbl) * DIM + j0 + rj] = hv;
            }
        }

        if (t == TSTEPS - 1) break;

        // ---- grid barrier (monotonic counters, reset by memset each launch) --
        __threadfence();          // make h stores visible at L2 before arrival
        __syncthreads();          // all threads' stores done before signaling
        if (tid == 0) {
            atomicAdd(&g_bar[t], 1u);
            volatile unsigned* p = &g_bar[t];
            while (*p < NCTA) { }
            __threadfence();      // acquire: order subsequent h reads
        }
        __syncthreads();
    }
}

// ============================================================================
extern "C" void kernel_launch(void* const* d_in, const int* in_sizes, int n_in,
                              void* d_out, int out_size)
{
    const float* x    = (const float*)d_in[0];   // [64,1024,512]
    const float* W    = (const float*)d_in[1];   // [512,512]
    const float* Wr   = (const float*)d_in[2];   // [512,512]
    const float* bias = (const float*)d_in[3];   // [512]
    float* out = (float*)d_out;                  // [64,512]

    float* xw_p; cudaGetSymbolAddress((void**)&xw_p, g_xw);
    void*  bar_p; cudaGetSymbolAddress(&bar_p, g_bar);
    void*  h_p;   cudaGetSymbolAddress(&h_p, g_h);

    // per-launch resets (graph-capturable, replay-safe)
    cudaMemsetAsync(bar_p, 0, sizeof(unsigned) * TSTEPS);
    cudaMemsetAsync(h_p, 0, sizeof(float) * BATCH * DIM);  // zero h_0 (buffer 0)

    dim3 ggrid((BATCH * TSTEPS) / BM, DIM / BN);           // 512 x 8
    gemm_xw_kernel<<<ggrid, 256>>>(x, W, bias, xw_p);

    rnn_persistent_kernel<<<NCTA, 256>>>(Wr, xw_p, out);
}